// round 16
// baseline (speedup 1.0000x reference)
#include <cuda_runtime.h>
#include <cuda_fp16.h>
#include <cstdint>

// Grouped GEMM, pure fp16 HMMA, fp32 accumulate.
// Tile 128x256, 512 threads (16 warps, warp 64x32), BK=64, 4-stage cp.async.
// Conv kernels: streaming loads/stores (.nc/.cs), 4x ILP.

static constexpr int HIDDEN = 2048;
static constexpr int FFN    = 8192;
static constexpr int MTOTAL = 16384;
static constexpr int NGROUPS = 8;

#define BM 128
#define BN 256
#define BK 64
#define NTHREADS 512
static constexpr int NCHUNK = HIDDEN / BK;   // 32

#define ROWA 144
#define ROWBB 528
#define OFF_A 0
#define OFF_B (BM * ROWA)                    // 18432
#define STAGE (OFF_B + BK * ROWBB)           // 52224
#define NSTAGE 4
#define SMEM_DYN (NSTAGE * STAGE)            // 208896

// ---- scratch ----
__device__ __half g_Ah[(size_t)MTOTAL * HIDDEN];
__device__ __half g_Wh[(size_t)NGROUPS * HIDDEN * FFN];   // [g][k][n] native

__constant__ int kGroupOff[9] = {0, 1024, 2560, 4608, 6656, 9216, 11264, 14336, 16384};

__device__ __forceinline__ uint32_t pack_h2(__half lo, __half hi) {
    return (uint32_t)__half_as_ushort(lo) | ((uint32_t)__half_as_ushort(hi) << 16);
}

// ================= conversions: 4 chains, streaming hints =================

__device__ __forceinline__ float4 ldcs4(const float* p) {
    float4 v;
    asm volatile("ld.global.nc.cs.v4.f32 {%0,%1,%2,%3}, [%4];"
                 : "=f"(v.x), "=f"(v.y), "=f"(v.z), "=f"(v.w)
                 : "l"(__cvta_generic_to_global(p)));
    return v;
}
__device__ __forceinline__ void stcs4(__half* p, uint4 v) {
    asm volatile("st.global.cs.v4.b32 [%0], {%1,%2,%3,%4};"
                 :: "l"(__cvta_generic_to_global(p)), "r"(v.x), "r"(v.y), "r"(v.z), "r"(v.w)
                 : "memory");
}

__device__ __forceinline__ void conv16(const float* __restrict__ src,
                                       __half* __restrict__ dst) {
    float4 v0 = ldcs4(src);
    float4 v1 = ldcs4(src + 4);
    float4 v2 = ldcs4(src + 8);
    float4 v3 = ldcs4(src + 12);
    uint4 o0, o1;
    o0.x = pack_h2(__float2half(v0.x), __float2half(v0.y));
    o0.y = pack_h2(__float2half(v0.z), __float2half(v0.w));
    o0.z = pack_h2(__float2half(v1.x), __float2half(v1.y));
    o0.w = pack_h2(__float2half(v1.z), __float2half(v1.w));
    o1.x = pack_h2(__float2half(v2.x), __float2half(v2.y));
    o1.y = pack_h2(__float2half(v2.z), __float2half(v2.w));
    o1.z = pack_h2(__float2half(v3.x), __float2half(v3.y));
    o1.w = pack_h2(__float2half(v3.z), __float2half(v3.w));
    stcs4(dst, o0);
    stcs4(dst + 8, o1);
}

__global__ void convA_kernel(const float* __restrict__ A, __half* __restrict__ Ah) {
    size_t i = ((size_t)blockIdx.x * blockDim.x + threadIdx.x) * 16;
    conv16(A + i, Ah + i);
}

__global__ void convW_kernel(const float* __restrict__ W, __half* __restrict__ Wh) {
    size_t i = ((size_t)blockIdx.x * blockDim.x + threadIdx.x) * 16;
    conv16(W + i, Wh + i);
}

// ================= GEMM =================

__device__ __forceinline__ uint32_t smem_u32(const void* p) {
    uint32_t a;
    asm("{ .reg .u64 t; cvta.to.shared.u64 t, %1; cvt.u32.u64 %0, t; }" : "=r"(a) : "l"(p));
    return a;
}
__device__ __forceinline__ void cp16(uint32_t dst, const void* src) {
    asm volatile("cp.async.cg.shared.global [%0], [%1], 16;\n"
                 :: "r"(dst), "l"(__cvta_generic_to_global(src)));
}
__device__ __forceinline__ void ldmx4(uint32_t* r, uint32_t addr) {
    asm volatile("ldmatrix.sync.aligned.m8n8.x4.shared.b16 {%0,%1,%2,%3}, [%4];"
                 : "=r"(r[0]), "=r"(r[1]), "=r"(r[2]), "=r"(r[3]) : "r"(addr));
}
__device__ __forceinline__ void ldmx4t(uint32_t* r, uint32_t addr) {
    asm volatile("ldmatrix.sync.aligned.m8n8.x4.trans.shared.b16 {%0,%1,%2,%3}, [%4];"
                 : "=r"(r[0]), "=r"(r[1]), "=r"(r[2]), "=r"(r[3]) : "r"(addr));
}
__device__ __forceinline__ void mma16816(float* c, const uint32_t* a, const uint32_t* b) {
    asm volatile(
        "mma.sync.aligned.m16n8k16.row.col.f32.f16.f16.f32 "
        "{%0,%1,%2,%3}, {%4,%5,%6,%7}, {%8,%9}, {%0,%1,%2,%3};"
        : "+f"(c[0]), "+f"(c[1]), "+f"(c[2]), "+f"(c[3])
        : "r"(a[0]), "r"(a[1]), "r"(a[2]), "r"(a[3]), "r"(b[0]), "r"(b[1]));
}
__device__ __forceinline__ void stcs2(float* p, float x, float y) {
    asm volatile("st.global.cs.v2.f32 [%0], {%1, %2};"
                 :: "l"(__cvta_generic_to_global(p)), "f"(x), "f"(y) : "memory");
}

__global__ __launch_bounds__(NTHREADS, 1)
void gemm_hmma_kernel(float* __restrict__ C) {
    extern __shared__ char smem[];
    const uint32_t sb = smem_u32(smem);

    const int tid  = threadIdx.x;
    const int warp = tid >> 5;       // 0..15
    const int lane = tid & 31;
    const int warpM = warp & 1;      // M offset *64
    const int warpN = warp >> 1;     // N offset *32

    // panel swizzle: 16 m-tiles per panel, column sweep
    const int bid   = blockIdx.x;    // 0..4095
    const int panel = bid >> 9;
    const int idx   = bid & 511;
    const int rowBase = (panel * 16 + (idx & 15)) * BM;
    const int colBase = (idx >> 4) * BN;

    int g = 0;
#pragma unroll
    for (int i = 1; i < 8; ++i)
        if (rowBase >= kGroupOff[i]) g = i;

    const __half* pA = g_Ah + (size_t)rowBase * HIDDEN;
    const __half* pB = g_Wh + (size_t)g * HIDDEN * FFN + colBase;   // k-row major

    // A copy: 128 rows x 8 chunks = 1024 slots -> 2/thread
    const int arow = tid >> 3;          // 0..63 (+64i)
    const int achk = tid & 7;
    const uint32_t soA = (uint32_t)(arow * ROWA + achk * 16);
    const size_t   goA = (size_t)arow * HIDDEN + achk * 8;
    // B copy: 64 k-rows x 32 chunks = 2048 slots -> 4/thread
    const int brow = tid >> 5;          // 0..15 (+16i)
    const int bchk = tid & 31;
    const uint32_t soB = (uint32_t)(brow * ROWBB + bchk * 16);
    const size_t   goB = (size_t)brow * FFN + bchk * 8;

    // ldmatrix offsets
    const uint32_t aOff = (uint32_t)((warpM * 64 + (lane & 15)) * ROWA + (lane >> 4) * 16);
    uint32_t bOff[2];
#pragma unroll
    for (int t = 0; t < 2; ++t)
        bOff[t] = (uint32_t)((lane & 15) * ROWBB
                             + (warpN * 32 + t * 16 + 8 * (lane >> 4)) * 2);

    float acc[4][4][4];
#pragma unroll
    for (int i = 0; i < 4; ++i)
#pragma unroll
        for (int n = 0; n < 4; ++n)
#pragma unroll
            for (int q = 0; q < 4; ++q) acc[i][n][q] = 0.0f;

#define ISSUE_LOADS(stagep, jj)                                                \
    do {                                                                       \
        const uint32_t st_ = (stagep);                                         \
        const size_t koA_ = (size_t)(jj) * BK;                                 \
        const size_t koB_ = (size_t)(jj) * BK * FFN;                           \
        _Pragma("unroll")                                                      \
        for (int i_ = 0; i_ < 2; ++i_)                                         \
            cp16(st_ + OFF_A + soA + i_ * 64 * ROWA,                           \
                 pA + goA + (size_t)i_ * 64 * HIDDEN + koA_);                  \
        _Pragma("unroll")                                                      \
        for (int i_ = 0; i_ < 4; ++i_)                                         \
            cp16(st_ + OFF_B + soB + i_ * 16 * ROWBB,                          \
                 pB + goB + (size_t)i_ * 16 * FFN + koB_);                     \
    } while (0)

    // prologue: stages 0..2
#pragma unroll
    for (int j = 0; j < NSTAGE - 1; ++j) {
        ISSUE_LOADS(sb + j * STAGE, j);
        asm volatile("cp.async.commit_group;" ::: "memory");
    }

    for (int j = 0; j < NCHUNK; ++j) {
        asm volatile("cp.async.wait_group %0;" :: "n"(NSTAGE - 2) : "memory");
        __syncthreads();

        if (j + NSTAGE - 1 < NCHUNK)
            ISSUE_LOADS(sb + ((j + NSTAGE - 1) % NSTAGE) * STAGE, j + NSTAGE - 1);
        asm volatile("cp.async.commit_group;" ::: "memory");

        const uint32_t st = sb + (j % NSTAGE) * STAGE;
#pragma unroll
        for (int s = 0; s < 4; ++s) {            // 4 k16-steps per BK=64
            uint32_t ah[4][4];
#pragma unroll
            for (int i = 0; i < 4; ++i)
                ldmx4(ah[i], st + OFF_A + aOff + i * 16 * ROWA + s * 32);
#pragma unroll
            for (int t = 0; t < 2; ++t) {
                uint32_t bh[4];
                ldmx4t(bh, st + OFF_B + bOff[t] + s * 16 * ROWBB);
#pragma unroll
                for (int i = 0; i < 4; ++i) {
                    mma16816(acc[i][2 * t],     ah[i], bh);
                    mma16816(acc[i][2 * t + 1], ah[i], bh + 2);
                }
            }
        }
    }
#undef ISSUE_LOADS

    // epilogue: warp tile 64x32, streaming stores
    const int mBase = rowBase + warpM * 64;
    const int nBase = colBase + warpN * 32;
#pragma unroll
    for (int i = 0; i < 4; ++i) {
#pragma unroll
        for (int n = 0; n < 4; ++n) {
            const int row0 = mBase + i * 16 + (lane >> 2);
            const int col  = nBase + n * 8 + (lane & 3) * 2;
            stcs2(C + (size_t)row0 * FFN + col,       acc[i][n][0], acc[i][n][1]);
            stcs2(C + (size_t)(row0 + 8) * FFN + col, acc[i][n][2], acc[i][n][3]);
        }
    }
}

// ================= launch =================

extern "C" void kernel_launch(void* const* d_in, const int* in_sizes, int n_in,
                              void* d_out, int out_size) {
    const float* A = (const float*)d_in[0];   // [16384, 2048]
    const float* W = (const float*)d_in[1];   // [8, 2048, 8192]
    float* C = (float*)d_out;                 // [16384, 8192]

    __half *Ah, *Wh;
    cudaGetSymbolAddress((void**)&Ah, g_Ah);
    cudaGetSymbolAddress((void**)&Wh, g_Wh);

    convA_kernel<<<(MTOTAL * HIDDEN) / (256 * 16), 256>>>(A, Ah);
    convW_kernel<<<(NGROUPS * HIDDEN * FFN) / (256 * 16), 256>>>(W, Wh);

    cudaFuncSetAttribute(gemm_hmma_kernel,
                         cudaFuncAttributeMaxDynamicSharedMemorySize, SMEM_DYN);
    gemm_hmma_kernel<<<(MTOTAL / BM) * (FFN / BN), NTHREADS, SMEM_DYN>>>(C);
}

// round 17
// speedup vs baseline: 1.0436x; 1.0436x over previous
#include <cuda_runtime.h>
#include <cuda_fp16.h>
#include <cstdint>

// Grouped GEMM, pure fp16 HMMA, fp32 accumulate. (R15 basin-floor config.)
// Tile 128x256, 512 threads (16 warps, warp 64x32), BK=64, 3-stage cp.async.
// Conversions fused into a single launch (A region then W region).

static constexpr int HIDDEN = 2048;
static constexpr int FFN    = 8192;
static constexpr int MTOTAL = 16384;
static constexpr int NGROUPS = 8;

#define BM 128
#define BN 256
#define BK 64
#define NTHREADS 512
static constexpr int NCHUNK = HIDDEN / BK;   // 32

#define ROWA 144
#define ROWBB 528
#define OFF_A 0
#define OFF_B (BM * ROWA)                    // 18432
#define STAGE (OFF_B + BK * ROWBB)           // 52224
#define NSTAGE 3
#define SMEM_DYN (NSTAGE * STAGE)            // 156672

static constexpr size_t A_ELEMS = (size_t)MTOTAL * HIDDEN;            // 33.5M
static constexpr size_t W_ELEMS = (size_t)NGROUPS * HIDDEN * FFN;     // 134M

// ---- scratch ----
__device__ __half g_Ah[A_ELEMS];
__device__ __half g_Wh[W_ELEMS];   // [g][k][n] native

__constant__ int kGroupOff[9] = {0, 1024, 2560, 4608, 6656, 9216, 11264, 14336, 16384};

__device__ __forceinline__ uint32_t pack_h2(__half lo, __half hi) {
    return (uint32_t)__half_as_ushort(lo) | ((uint32_t)__half_as_ushort(hi) << 16);
}

// ================= fused conversion: 4 chains/thread, .cs stores ===========

__device__ __forceinline__ void stcs4h(__half* p, uint4 v) {
    asm volatile("st.global.cs.v4.b32 [%0], {%1,%2,%3,%4};"
                 :: "l"(__cvta_generic_to_global(p)), "r"(v.x), "r"(v.y), "r"(v.z), "r"(v.w)
                 : "memory");
}

__device__ __forceinline__ void conv16(const float* __restrict__ src,
                                       __half* __restrict__ dst) {
    float4 v0 = *(const float4*)(src);
    float4 v1 = *(const float4*)(src + 4);
    float4 v2 = *(const float4*)(src + 8);
    float4 v3 = *(const float4*)(src + 12);
    uint4 o0, o1;
    o0.x = pack_h2(__float2half(v0.x), __float2half(v0.y));
    o0.y = pack_h2(__float2half(v0.z), __float2half(v0.w));
    o0.z = pack_h2(__float2half(v1.x), __float2half(v1.y));
    o0.w = pack_h2(__float2half(v1.z), __float2half(v1.w));
    o1.x = pack_h2(__float2half(v2.x), __float2half(v2.y));
    o1.y = pack_h2(__float2half(v2.z), __float2half(v2.w));
    o1.z = pack_h2(__float2half(v3.x), __float2half(v3.y));
    o1.w = pack_h2(__float2half(v3.z), __float2half(v3.w));
    stcs4h(dst, o0);
    stcs4h(dst + 8, o1);
}

__global__ void conv_fused_kernel(const float* __restrict__ A,
                                  const float* __restrict__ W,
                                  __half* __restrict__ Ah,
                                  __half* __restrict__ Wh) {
    size_t i = ((size_t)blockIdx.x * blockDim.x + threadIdx.x) * 16;
    if (i < A_ELEMS) {
        conv16(A + i, Ah + i);
    } else {
        size_t j = i - A_ELEMS;
        conv16(W + j, Wh + j);
    }
}

// ================= GEMM =================

__device__ __forceinline__ uint32_t smem_u32(const void* p) {
    uint32_t a;
    asm("{ .reg .u64 t; cvta.to.shared.u64 t, %1; cvt.u32.u64 %0, t; }" : "=r"(a) : "l"(p));
    return a;
}
__device__ __forceinline__ void cp16(uint32_t dst, const void* src) {
    asm volatile("cp.async.cg.shared.global [%0], [%1], 16;\n"
                 :: "r"(dst), "l"(__cvta_generic_to_global(src)));
}
__device__ __forceinline__ void ldmx4(uint32_t* r, uint32_t addr) {
    asm volatile("ldmatrix.sync.aligned.m8n8.x4.shared.b16 {%0,%1,%2,%3}, [%4];"
                 : "=r"(r[0]), "=r"(r[1]), "=r"(r[2]), "=r"(r[3]) : "r"(addr));
}
__device__ __forceinline__ void ldmx4t(uint32_t* r, uint32_t addr) {
    asm volatile("ldmatrix.sync.aligned.m8n8.x4.trans.shared.b16 {%0,%1,%2,%3}, [%4];"
                 : "=r"(r[0]), "=r"(r[1]), "=r"(r[2]), "=r"(r[3]) : "r"(addr));
}
__device__ __forceinline__ void mma16816(float* c, const uint32_t* a, const uint32_t* b) {
    asm volatile(
        "mma.sync.aligned.m16n8k16.row.col.f32.f16.f16.f32 "
        "{%0,%1,%2,%3}, {%4,%5,%6,%7}, {%8,%9}, {%0,%1,%2,%3};"
        : "+f"(c[0]), "+f"(c[1]), "+f"(c[2]), "+f"(c[3])
        : "r"(a[0]), "r"(a[1]), "r"(a[2]), "r"(a[3]), "r"(b[0]), "r"(b[1]));
}
__device__ __forceinline__ void stcs2(float* p, float x, float y) {
    asm volatile("st.global.cs.v2.f32 [%0], {%1, %2};"
                 :: "l"(__cvta_generic_to_global(p)), "f"(x), "f"(y) : "memory");
}

__global__ __launch_bounds__(NTHREADS, 1)
void gemm_hmma_kernel(float* __restrict__ C) {
    extern __shared__ char smem[];
    const uint32_t sb = smem_u32(smem);

    const int tid  = threadIdx.x;
    const int warp = tid >> 5;       // 0..15
    const int lane = tid & 31;
    const int warpM = warp & 1;      // M offset *64
    const int warpN = warp >> 1;     // N offset *32

    // panel swizzle: 16 m-tiles per panel, column sweep
    const int bid   = blockIdx.x;    // 0..4095
    const int panel = bid >> 9;
    const int idx   = bid & 511;
    const int rowBase = (panel * 16 + (idx & 15)) * BM;
    const int colBase = (idx >> 4) * BN;

    int g = 0;
#pragma unroll
    for (int i = 1; i < 8; ++i)
        if (rowBase >= kGroupOff[i]) g = i;

    const __half* pA = g_Ah + (size_t)rowBase * HIDDEN;
    const __half* pB = g_Wh + (size_t)g * HIDDEN * FFN + colBase;   // k-row major

    // A copy: 128 rows x 8 chunks = 1024 slots -> 2/thread
    const int arow = tid >> 3;          // 0..63 (+64i)
    const int achk = tid & 7;
    const uint32_t soA = (uint32_t)(arow * ROWA + achk * 16);
    const size_t   goA = (size_t)arow * HIDDEN + achk * 8;
    // B copy: 64 k-rows x 32 chunks = 2048 slots -> 4/thread
    const int brow = tid >> 5;          // 0..15 (+16i)
    const int bchk = tid & 31;
    const uint32_t soB = (uint32_t)(brow * ROWBB + bchk * 16);
    const size_t   goB = (size_t)brow * FFN + bchk * 8;

    // ldmatrix offsets
    const uint32_t aOff = (uint32_t)((warpM * 64 + (lane & 15)) * ROWA + (lane >> 4) * 16);
    uint32_t bOff[2];
#pragma unroll
    for (int t = 0; t < 2; ++t)
        bOff[t] = (uint32_t)((lane & 15) * ROWBB
                             + (warpN * 32 + t * 16 + 8 * (lane >> 4)) * 2);

    float acc[4][4][4];
#pragma unroll
    for (int i = 0; i < 4; ++i)
#pragma unroll
        for (int n = 0; n < 4; ++n)
#pragma unroll
            for (int q = 0; q < 4; ++q) acc[i][n][q] = 0.0f;

#define ISSUE_LOADS(stagep, jj)                                                \
    do {                                                                       \
        const uint32_t st_ = (stagep);                                         \
        const size_t koA_ = (size_t)(jj) * BK;                                 \
        const size_t koB_ = (size_t)(jj) * BK * FFN;                           \
        _Pragma("unroll")                                                      \
        for (int i_ = 0; i_ < 2; ++i_)                                         \
            cp16(st_ + OFF_A + soA + i_ * 64 * ROWA,                           \
                 pA + goA + (size_t)i_ * 64 * HIDDEN + koA_);                  \
        _Pragma("unroll")                                                      \
        for (int i_ = 0; i_ < 4; ++i_)                                         \
            cp16(st_ + OFF_B + soB + i_ * 16 * ROWBB,                          \
                 pB + goB + (size_t)i_ * 16 * FFN + koB_);                     \
    } while (0)

    // prologue: stages 0,1
#pragma unroll
    for (int j = 0; j < NSTAGE - 1; ++j) {
        ISSUE_LOADS(sb + j * STAGE, j);
        asm volatile("cp.async.commit_group;" ::: "memory");
    }

    for (int j = 0; j < NCHUNK; ++j) {
        asm volatile("cp.async.wait_group %0;" :: "n"(NSTAGE - 2) : "memory");
        __syncthreads();

        if (j + NSTAGE - 1 < NCHUNK)
            ISSUE_LOADS(sb + ((j + NSTAGE - 1) % NSTAGE) * STAGE, j + NSTAGE - 1);
        asm volatile("cp.async.commit_group;" ::: "memory");

        const uint32_t st = sb + (j % NSTAGE) * STAGE;
#pragma unroll
        for (int s = 0; s < 4; ++s) {            // 4 k16-steps per BK=64
            uint32_t ah[4][4];
#pragma unroll
            for (int i = 0; i < 4; ++i)
                ldmx4(ah[i], st + OFF_A + aOff + i * 16 * ROWA + s * 32);
#pragma unroll
            for (int t = 0; t < 2; ++t) {
                uint32_t bh[4];
                ldmx4t(bh, st + OFF_B + bOff[t] + s * 16 * ROWBB);
#pragma unroll
                for (int i = 0; i < 4; ++i) {
                    mma16816(acc[i][2 * t],     ah[i], bh);
                    mma16816(acc[i][2 * t + 1], ah[i], bh + 2);
                }
            }
        }
    }
#undef ISSUE_LOADS

    // epilogue: warp tile 64x32, streaming stores (C is write-once)
    const int mBase = rowBase + warpM * 64;
    const int nBase = colBase + warpN * 32;
#pragma unroll
    for (int i = 0; i < 4; ++i) {
#pragma unroll
        for (int n = 0; n < 4; ++n) {
            const int row0 = mBase + i * 16 + (lane >> 2);
            const int col  = nBase + n * 8 + (lane & 3) * 2;
            stcs2(C + (size_t)row0 * FFN + col,       acc[i][n][0], acc[i][n][1]);
            stcs2(C + (size_t)(row0 + 8) * FFN + col, acc[i][n][2], acc[i][n][3]);
        }
    }
}

// ================= launch =================

extern "C" void kernel_launch(void* const* d_in, const int* in_sizes, int n_in,
                              void* d_out, int out_size) {
    const float* A = (const float*)d_in[0];   // [16384, 2048]
    const float* W = (const float*)d_in[1];   // [8, 2048, 8192]
    float* C = (float*)d_out;                 // [16384, 8192]

    __half *Ah, *Wh;
    cudaGetSymbolAddress((void**)&Ah, g_Ah);
    cudaGetSymbolAddress((void**)&Wh, g_Wh);

    const size_t totalElems = A_ELEMS + W_ELEMS;        // both multiples of 4096
    conv_fused_kernel<<<(unsigned)(totalElems / (256 * 16)), 256>>>(A, W, Ah, Wh);

    cudaFuncSetAttribute(gemm_hmma_kernel,
                         cudaFuncAttributeMaxDynamicSharedMemorySize, SMEM_DYN);
    gemm_hmma_kernel<<<(MTOTAL / BM) * (FFN / BN), NTHREADS, SMEM_DYN>>>(C);
}